// round 14
// baseline (speedup 1.0000x reference)
#include <cuda_runtime.h>
#include <math.h>

#define NP     4096
#define TOTAL  65536
#define ROWS   32
#define NB     256
#define LOV    (-5.0f)
#define HIV    (5.0f)
#define WBIN   ((HIV - LOV) / NB)
#define INVW   ((float)NB / (HIV - LOV))
#define PAD    3
#define WMIN   384
#define WCAP   576                 // staged window cap in points (9 KB)
#define NBLK   (2 * TOTAL / 32)    // 4096 one-warp blocks
#define FULLM  0xFFFFFFFFu

__device__ float4 g_sorted[2 * TOTAL];
__device__ int    g_binstart[ROWS][NB + 1];
__device__ float  g_partial[NBLK];

__device__ __forceinline__ int binof(float v) {
    int b = (int)((v - LOV) * INVW);
    return min(max(b, 0), NB - 1);
}

// One block per (tensor,batch) row: hist + scan + scatter, block-local.
__global__ __launch_bounds__(512) void prep_kernel(const float* __restrict__ x,
                                                   const float* __restrict__ y) {
    int row = blockIdx.x;
    const float* src = ((row >= 16) ? y : x) + (size_t)(row & 15) * NP * 3;
    __shared__ int h[NB];
    __shared__ int base[NB];
    __shared__ int cnt[NB];
    int tid = threadIdx.x;

    if (tid < NB) h[tid] = 0;
    __syncthreads();

    float2 r[12];
    const float2* s2 = (const float2*)(src + 24 * tid);
    #pragma unroll
    for (int i = 0; i < 12; i++) r[i] = s2[i];

    int bins[8];
    #pragma unroll
    for (int p = 0; p < 8; p++) {
        float vx = ((const float*)r)[3 * p];
        bins[p] = binof(vx);
        atomicAdd(&h[bins[p]], 1);
    }
    __syncthreads();

    int v = 0;
    if (tid < NB) { v = h[tid]; base[tid] = v; }
    __syncthreads();
    #pragma unroll
    for (int off = 1; off < NB; off <<= 1) {
        int t = 0;
        if (tid < NB && tid >= off) t = base[tid - off];
        __syncthreads();
        if (tid < NB) base[tid] += t;
        __syncthreads();
    }
    if (tid < NB) {
        int ex = base[tid] - v;
        g_binstart[row][tid] = ex;
        base[tid] = ex;
        cnt[tid] = 0;
        if (tid == NB - 1) g_binstart[row][NB] = ex + v;
    }
    __syncthreads();

    float4* dst = g_sorted + (size_t)row * NP;
    #pragma unroll
    for (int p = 0; p < 8; p++) {
        const float* f = (const float*)r + 3 * p;
        float a = f[0], c = f[1], d = f[2];
        int pos = base[bins[p]] + atomicAdd(&cnt[bins[p]], 1);
        dst[pos] = make_float4(a, c, d, 0.5f * (a * a + c * c + d * d));
    }
}

// One warp per block. No __syncthreads anywhere.
__global__ __launch_bounds__(32) void chamfer_kernel() {
    __shared__ float4 swin[WCAP];

    int blk = blockIdx.x;                 // 4096 blocks
    int dir = blk >> 11;
    int b   = (blk >> 7) & 15;
    int qt  = blk & 127;                  // 128 tiles of 32 queries
    int lane = threadIdx.x;

    int qRow  = dir ? (16 + b) : b;
    int dbRow = dir ? b : (16 + b);
    const float4* db = g_sorted + (size_t)dbRow * NP;
    const int*    bs = g_binstart[dbRow];

    float4 q = g_sorted[(size_t)qRow * NP + qt * 32 + lane];

    // Warp window: query-bin span + PAD, count-extended to WMIN.
    int myBin = binof(q.x);
    int kL = (int)__reduce_min_sync(FULLM, (unsigned)myBin);
    int kR = (int)__reduce_max_sync(FULLM, (unsigned)myBin);
    kL = max(kL - PAD, 0);
    kR = min(kR + PAD, NB - 1);
    int lo = __ldg(bs + kL);
    int hi = __ldg(bs + kR + 1);
    while (hi - lo < WMIN && (kL > 0 || kR < NB - 1)) {
        if (kL > 0) { kL--; lo = __ldg(bs + kL); }
        if (kR < NB - 1) { kR++; hi = __ldg(bs + kR + 1); }
    }
    int cnt = min(hi - lo, WCAP);
    bool clampedR = (hi - lo > WCAP);
    int scanLo = lo, scanHi = lo + cnt;

    // Stage own window (coalesced LDG -> STS).
    for (int j = lane; j < cnt; j += 32) swin[j] = db[lo + j];
    __syncwarp();

    // Scan staged window: min of t_j = 0.5|s_j|^2 - q.s_j
    float m0 = 1e30f, m1 = 1e30f, m2 = 1e30f, m3 = 1e30f;
    int j = 0;
    for (; j + 4 <= cnt; j += 4) {
        float4 p0 = swin[j];
        float4 p1 = swin[j + 1];
        float4 p2 = swin[j + 2];
        float4 p3 = swin[j + 3];
        m0 = fminf(m0, fmaf(-q.x, p0.x, fmaf(-q.y, p0.y, fmaf(-q.z, p0.z, p0.w))));
        m1 = fminf(m1, fmaf(-q.x, p1.x, fmaf(-q.y, p1.y, fmaf(-q.z, p1.z, p1.w))));
        m2 = fminf(m2, fmaf(-q.x, p2.x, fmaf(-q.y, p2.y, fmaf(-q.z, p2.z, p2.w))));
        m3 = fminf(m3, fmaf(-q.x, p3.x, fmaf(-q.y, p3.y, fmaf(-q.z, p3.z, p3.w))));
    }
    for (; j < cnt; ++j) {
        float4 p = swin[j];
        m0 = fminf(m0, fmaf(-q.x, p.x, fmaf(-q.y, p.y, fmaf(-q.z, p.z, p.w))));
    }
    float m = fminf(fminf(m0, m1), fminf(m2, m3));

    // Exact per-lane exclusion bound at window bin edges.
    float thr   = q.w + m;                      // 0.5 * d_best^2 upper bound
    float edgeL = LOV + (float)kL * WBIN;
    float edgeR = LOV + (float)(kR + 1) * WBIN;
    float gl = fmaxf(q.x - edgeL, 0.0f);
    float gr = fmaxf(edgeR - q.x, 0.0f);
    bool dL = (kL == 0)      || (0.5f * gl * gl >= thr);
    bool dR = !clampedR && ((kR == NB - 1) || (0.5f * gr * gr >= thr));

    float d = sqrtf(1e-6f + fmaxf(2.0f * thr, 0.0f));

    // Warp-local exact phase 2 for spilled lanes (shuffle-driven, deterministic).
    unsigned spillMask = __ballot_sync(FULLM, !(dL && dR));
    while (spillMask) {
        int t = __ffs(spillMask) - 1;
        spillMask &= spillMask - 1;
        float q2x = __shfl_sync(FULLM, q.x, t);
        float q2y = __shfl_sync(FULLM, q.y, t);
        float q2z = __shfl_sync(FULLM, q.z, t);
        float q2w = __shfl_sync(FULLM, q.w, t);
        float mm  = __shfl_sync(FULLM, m, t);

        float d1 = sqrtf(fmaxf(2.0f * (q2w + mm), 0.0f)) * 1.0005f + 1e-5f;
        int lo2 = __ldg(bs + binof(q2x - d1));
        int hi2 = __ldg(bs + binof(q2x + d1) + 1);

        // Skip [scanLo, scanHi) (already scanned).
        int hA = min(hi2, scanLo);
        for (int jj = lo2 + lane; jj < hA; jj += 32) {
            float4 p = __ldg(&db[jj]);
            mm = fminf(mm, fmaf(-q2x, p.x, fmaf(-q2y, p.y, fmaf(-q2z, p.z, p.w))));
        }
        int lB = max(lo2, scanHi);
        for (int jj = lB + lane; jj < hi2; jj += 32) {
            float4 p = __ldg(&db[jj]);
            mm = fminf(mm, fmaf(-q2x, p.x, fmaf(-q2y, p.y, fmaf(-q2z, p.z, p.w))));
        }
        #pragma unroll
        for (int o = 16; o; o >>= 1)
            mm = fminf(mm, __shfl_xor_sync(FULLM, mm, o));
        float dn = sqrtf(1e-6f + fmaxf(2.0f * (q2w + mm), 0.0f));
        if (lane == t) d = dn;
    }

    // Deterministic warp butterfly sum.
    #pragma unroll
    for (int o = 16; o; o >>= 1)
        d += __shfl_xor_sync(FULLM, d, o);
    if (lane == 0) g_partial[blk] = d;
}

__global__ __launch_bounds__(1024) void finalize_kernel(float* __restrict__ out) {
    __shared__ float s[1024];
    int tid = threadIdx.x;
    float v = 0.0f;
    #pragma unroll
    for (int i = 0; i < 4; i++) v += g_partial[tid + 1024 * i];
    s[tid] = v;
    __syncthreads();
    #pragma unroll
    for (int st = 512; st > 0; st >>= 1) {
        if (tid < st) s[tid] += s[tid + st];
        __syncthreads();
    }
    if (tid == 0) out[0] = s[0] * (1.0f / (float)TOTAL);
}

extern "C" void kernel_launch(void* const* d_in, const int* in_sizes, int n_in,
                              void* d_out, int out_size) {
    const float* x = (const float*)d_in[0];
    const float* y = (const float*)d_in[1];
    float* out = (float*)d_out;

    prep_kernel<<<ROWS, 512>>>(x, y);
    chamfer_kernel<<<NBLK, 32>>>();
    finalize_kernel<<<1, 1024>>>(out);
}

// round 15
// speedup vs baseline: 1.0584x; 1.0584x over previous
#include <cuda_runtime.h>
#include <math.h>

#define NP     4096
#define TOTAL  65536
#define ROWS   32
#define NB     256
#define LOV    (-5.0f)
#define HIV    (5.0f)
#define WBIN   ((HIV - LOV) / NB)
#define INVW   ((float)NB / (HIV - LOV))
#define PAD    2
#define WMIN   320
#define WCAP   1536
#define BT     128
#define QPB    128
#define NBLK   (2 * TOTAL / QPB)   // 1024
#define FULLM  0xFFFFFFFFu

__device__ float4 g_sorted[2 * TOTAL];
__device__ int    g_hist8[ROWS][8][NB];
__device__ int    g_segstart[ROWS][8][NB];
__device__ int    g_binstart[ROWS][NB + 1];
__device__ float  g_partial[NBLK];

__device__ __forceinline__ int binof(float v) {
    int b = (int)((v - LOV) * INVW);
    return min(max(b, 0), NB - 1);
}

__global__ __launch_bounds__(256) void hist_kernel(const float* __restrict__ x,
                                                   const float* __restrict__ y) {
    int row = blockIdx.x >> 3, seg = blockIdx.x & 7;
    const float* src = ((row >= 16) ? y : x) + (size_t)(row & 15) * NP * 3;
    __shared__ int h[NB];
    int tid = threadIdx.x;
    h[tid] = 0;
    __syncthreads();
    int p0 = seg * 512 + tid * 2;
    atomicAdd(&h[binof(src[3 * p0])], 1);
    atomicAdd(&h[binof(src[3 * (p0 + 1)])], 1);
    __syncthreads();
    g_hist8[row][seg][tid] = h[tid];
}

// Per-row: bin totals -> scan -> binstart; then per-seg exclusive starts.
__global__ __launch_bounds__(NB) void prefix_kernel() {
    int row = blockIdx.x, tid = threadIdx.x;
    __shared__ int s[NB];
    int hv[8];
    int v = 0;
    #pragma unroll
    for (int k = 0; k < 8; k++) { hv[k] = g_hist8[row][k][tid]; v += hv[k]; }
    s[tid] = v;
    __syncthreads();
    #pragma unroll
    for (int off = 1; off < NB; off <<= 1) {
        int t = (tid >= off) ? s[tid - off] : 0;
        __syncthreads();
        s[tid] += t;
        __syncthreads();
    }
    int run = s[tid] - v;
    g_binstart[row][tid] = run;
    if (tid == NB - 1) g_binstart[row][NB] = s[tid];
    #pragma unroll
    for (int k = 0; k < 8; k++) { g_segstart[row][k][tid] = run; run += hv[k]; }
}

// No global atomics: smem-local ranks + per-segment start offsets.
__global__ __launch_bounds__(256) void scatter_kernel(const float* __restrict__ x,
                                                      const float* __restrict__ y) {
    int row = blockIdx.x >> 3, seg = blockIdx.x & 7;
    const float* src = ((row >= 16) ? y : x) + (size_t)(row & 15) * NP * 3;
    __shared__ int cnt[NB];
    int tid = threadIdx.x;
    cnt[tid] = 0;
    __syncthreads();
    int p0 = seg * 512 + tid * 2;
    const float2* s2 = (const float2*)(src + 3 * p0);
    float2 ab = s2[0], ca = s2[1], bc = s2[2];
    float4* dst = g_sorted + (size_t)row * NP;
    {
        int bin = binof(ab.x);
        int pos = g_segstart[row][seg][bin] + atomicAdd(&cnt[bin], 1);
        dst[pos] = make_float4(ab.x, ab.y, ca.x,
                               0.5f * (ab.x * ab.x + ab.y * ab.y + ca.x * ca.x));
    }
    {
        int bin = binof(ca.y);
        int pos = g_segstart[row][seg][bin] + atomicAdd(&cnt[bin], 1);
        dst[pos] = make_float4(ca.y, bc.x, bc.y,
                               0.5f * (ca.y * ca.y + bc.x * bc.x + bc.y * bc.y));
    }
}

__global__ __launch_bounds__(BT) void chamfer_kernel() {
    __shared__ int    sbs[NB + 1];
    __shared__ float4 swin[WCAP];
    __shared__ float4 qbuf[QPB];
    __shared__ float  sdist[QPB];
    __shared__ int    slist[QPB];
    __shared__ float  smin[QPB];
    __shared__ int    scount;
    __shared__ int    wKL[4], wKR[4];
    __shared__ int    wScanLo[4], wScanHi[4];
    __shared__ int    bWinLo, bWinCnt;

    int blk = blockIdx.x;                 // 1024 blocks
    int dir = blk >> 9;
    int b   = (blk >> 5) & 15;
    int qt  = blk & 31;
    int tid = threadIdx.x;
    int lane = tid & 31;
    int wid  = tid >> 5;

    int qRow  = dir ? (16 + b) : b;
    int dbRow = dir ? b : (16 + b);
    const float4* db = g_sorted + (size_t)dbRow * NP;

    for (int k = tid; k <= NB; k += BT) sbs[k] = g_binstart[dbRow][k];
    if (tid == 0) scount = 0;

    float4 q = g_sorted[(size_t)qRow * NP + qt * QPB + tid];
    qbuf[tid] = q;
    __syncthreads();

    // Per-warp window: span of the warp's 32 queries + PAD, count-extended.
    int myBin = binof(q.x);
    int kL = (int)__reduce_min_sync(FULLM, (unsigned)myBin);
    int kR = (int)__reduce_max_sync(FULLM, (unsigned)myBin);
    kL = max(kL - PAD, 0);
    kR = min(kR + PAD, NB - 1);
    while (sbs[kR + 1] - sbs[kL] < WMIN && (kL > 0 || kR < NB - 1)) {
        if (kL > 0) kL--;
        if (kR < NB - 1) kR++;
    }
    if (lane == 0) { wKL[wid] = kL; wKR[wid] = kR; }
    __syncthreads();

    if (tid == 0) {
        int kLb = min(min(wKL[0], wKL[1]), min(wKL[2], wKL[3]));
        int kRb = max(max(wKR[0], wKR[1]), max(wKR[2], wKR[3]));
        int lo  = sbs[kLb];
        bWinLo  = lo;
        bWinCnt = min(sbs[kRb + 1] - lo, WCAP);
    }
    __syncthreads();
    int winLo = bWinLo, winCnt = bWinCnt;

    for (int j = tid; j < winCnt; j += BT) swin[j] = db[winLo + j];

    int sLo = max(sbs[kL] - winLo, 0);
    int sHi = min(sbs[kR + 1] - winLo, winCnt);
    bool clampedL = (sbs[kL] < winLo);
    bool clampedR = (sbs[kR + 1] > winLo + winCnt);
    if (lane == 0) { wScanLo[wid] = winLo + sLo; wScanHi[wid] = winLo + sHi; }
    __syncthreads();

    // min over window of t_j = 0.5|s_j|^2 - q.s_j
    float m0 = 1e30f, m1 = 1e30f, m2 = 1e30f, m3 = 1e30f;
    int j = sLo;
    for (; j + 4 <= sHi; j += 4) {
        float4 p0 = swin[j];
        float4 p1 = swin[j + 1];
        float4 p2 = swin[j + 2];
        float4 p3 = swin[j + 3];
        m0 = fminf(m0, fmaf(-q.x, p0.x, fmaf(-q.y, p0.y, fmaf(-q.z, p0.z, p0.w))));
        m1 = fminf(m1, fmaf(-q.x, p1.x, fmaf(-q.y, p1.y, fmaf(-q.z, p1.z, p1.w))));
        m2 = fminf(m2, fmaf(-q.x, p2.x, fmaf(-q.y, p2.y, fmaf(-q.z, p2.z, p2.w))));
        m3 = fminf(m3, fmaf(-q.x, p3.x, fmaf(-q.y, p3.y, fmaf(-q.z, p3.z, p3.w))));
    }
    for (; j < sHi; ++j) {
        float4 p0 = swin[j];
        m0 = fminf(m0, fmaf(-q.x, p0.x, fmaf(-q.y, p0.y, fmaf(-q.z, p0.z, p0.w))));
    }
    float m = fminf(fminf(m0, m1), fminf(m2, m3));

    // Exact per-lane exclusion bound at warp-window bin edges.
    float thr   = q.w + m;                      // 0.5 * d_best^2 upper bound
    float edgeL = LOV + (float)kL * WBIN;
    float edgeR = LOV + (float)(kR + 1) * WBIN;
    float gl = fmaxf(q.x - edgeL, 0.0f);
    float gr = fmaxf(edgeR - q.x, 0.0f);
    bool dL = !clampedL && ((kL == 0)      || (0.5f * gl * gl >= thr));
    bool dR = !clampedR && ((kR == NB - 1) || (0.5f * gr * gr >= thr));

    sdist[tid] = sqrtf(1e-6f + fmaxf(2.0f * thr, 0.0f));

    bool need = !(dL && dR);
    unsigned mk = __ballot_sync(FULLM, need);
    int nneed = __popc(mk);
    if (nneed) {
        int base = 0;
        if (lane == 0) base = atomicAdd(&scount, nneed);
        base = __shfl_sync(FULLM, base, 0);
        if (need) {
            int rank = __popc(mk & ((1u << lane) - 1));
            slist[base + rank] = tid;
            smin[base + rank] = m;
        }
    }
    __syncthreads();

    // Block-local exact phase 2: one warp per spilled query; skip scanned range.
    int ns = scount;
    for (int i = wid; i < ns; i += BT / 32) {
        int t = slist[i];
        float mm = smin[i];
        float4 q2 = qbuf[t];
        int w2 = t >> 5;
        int skLo = wScanLo[w2], skHi = wScanHi[w2];

        float d1 = sqrtf(fmaxf(2.0f * (q2.w + mm), 0.0f)) * 1.0005f + 1e-5f;
        int lo2 = sbs[binof(q2.x - d1)];
        int hi2 = sbs[binof(q2.x + d1) + 1];

        int hA = min(hi2, skLo);
        for (int jj = lo2 + lane; jj < hA; jj += 32) {
            float4 p = __ldg(&db[jj]);
            mm = fminf(mm, fmaf(-q2.x, p.x, fmaf(-q2.y, p.y, fmaf(-q2.z, p.z, p.w))));
        }
        int lB = max(lo2, skHi);
        for (int jj = lB + lane; jj < hi2; jj += 32) {
            float4 p = __ldg(&db[jj]);
            mm = fminf(mm, fmaf(-q2.x, p.x, fmaf(-q2.y, p.y, fmaf(-q2.z, p.z, p.w))));
        }
        #pragma unroll
        for (int o = 16; o; o >>= 1)
            mm = fminf(mm, __shfl_xor_sync(FULLM, mm, o));
        if (lane == 0)
            sdist[t] = sqrtf(1e-6f + fmaxf(2.0f * (q2.w + mm), 0.0f));
    }
    __syncthreads();

    // Deterministic fixed-tree reduction over the block's 128 distances.
    #pragma unroll
    for (int st = BT / 2; st > 0; st >>= 1) {
        if (tid < st) sdist[tid] += sdist[tid + st];
        __syncthreads();
    }
    if (tid == 0) g_partial[blk] = sdist[0];
}

__global__ __launch_bounds__(512) void finalize_kernel(float* __restrict__ out) {
    __shared__ float s[512];
    int tid = threadIdx.x;
    s[tid] = g_partial[tid] + g_partial[tid + 512];
    __syncthreads();
    #pragma unroll
    for (int st = 256; st > 0; st >>= 1) {
        if (tid < st) s[tid] += s[tid + st];
        __syncthreads();
    }
    if (tid == 0) out[0] = s[0] * (1.0f / (float)TOTAL);
}

extern "C" void kernel_launch(void* const* d_in, const int* in_sizes, int n_in,
                              void* d_out, int out_size) {
    const float* x = (const float*)d_in[0];
    const float* y = (const float*)d_in[1];
    float* out = (float*)d_out;

    hist_kernel<<<256, 256>>>(x, y);
    prefix_kernel<<<ROWS, NB>>>();
    scatter_kernel<<<256, 256>>>(x, y);
    chamfer_kernel<<<NBLK, BT>>>();
    finalize_kernel<<<1, 512>>>(out);
}

// round 16
// speedup vs baseline: 1.1528x; 1.0891x over previous
#include <cuda_runtime.h>
#include <math.h>

#define NP     4096
#define TOTAL  65536
#define ROWS   32
#define NB     256
#define LOV    (-5.0f)
#define HIV    (5.0f)
#define WBIN   ((HIV - LOV) / NB)
#define INVW   ((float)NB / (HIV - LOV))
#define PAD    3
#define WMIN   384
#define WCAP   1536
#define BT     128
#define QPB    128
#define NBLK   (2 * TOTAL / QPB)   // 1024
#define FULLM  0xFFFFFFFFu

__device__ float4 g_sorted[2 * TOTAL];
__device__ int    g_hist8[ROWS][8][NB];
__device__ int    g_segstart[ROWS][8][NB];
__device__ int    g_binstart[ROWS][NB + 1];
__device__ float  g_partial[NBLK];
__device__ unsigned g_done;

__device__ __forceinline__ int binof(float v) {
    int b = (int)((v - LOV) * INVW);
    return min(max(b, 0), NB - 1);
}

__global__ __launch_bounds__(256) void hist_kernel(const float* __restrict__ x,
                                                   const float* __restrict__ y) {
    int row = blockIdx.x >> 3, seg = blockIdx.x & 7;
    const float* src = ((row >= 16) ? y : x) + (size_t)(row & 15) * NP * 3;
    __shared__ int h[NB];
    int tid = threadIdx.x;
    h[tid] = 0;
    __syncthreads();
    int p0 = seg * 512 + tid * 2;
    atomicAdd(&h[binof(src[3 * p0])], 1);
    atomicAdd(&h[binof(src[3 * (p0 + 1)])], 1);
    __syncthreads();
    g_hist8[row][seg][tid] = h[tid];
}

// Per-row: bin totals -> scan -> binstart; then per-seg exclusive starts.
// Also resets the finalize ticket for this replay.
__global__ __launch_bounds__(NB) void prefix_kernel() {
    int row = blockIdx.x, tid = threadIdx.x;
    if (row == 0 && tid == 0) g_done = 0;
    __shared__ int s[NB];
    int hv[8];
    int v = 0;
    #pragma unroll
    for (int k = 0; k < 8; k++) { hv[k] = g_hist8[row][k][tid]; v += hv[k]; }
    s[tid] = v;
    __syncthreads();
    #pragma unroll
    for (int off = 1; off < NB; off <<= 1) {
        int t = (tid >= off) ? s[tid - off] : 0;
        __syncthreads();
        s[tid] += t;
        __syncthreads();
    }
    int run = s[tid] - v;
    g_binstart[row][tid] = run;
    if (tid == NB - 1) g_binstart[row][NB] = s[tid];
    #pragma unroll
    for (int k = 0; k < 8; k++) { g_segstart[row][k][tid] = run; run += hv[k]; }
}

// No global atomics: smem-local ranks + per-segment start offsets.
__global__ __launch_bounds__(256) void scatter_kernel(const float* __restrict__ x,
                                                      const float* __restrict__ y) {
    int row = blockIdx.x >> 3, seg = blockIdx.x & 7;
    const float* src = ((row >= 16) ? y : x) + (size_t)(row & 15) * NP * 3;
    __shared__ int cnt[NB];
    int tid = threadIdx.x;
    cnt[tid] = 0;
    __syncthreads();
    int p0 = seg * 512 + tid * 2;
    const float2* s2 = (const float2*)(src + 3 * p0);
    float2 ab = s2[0], ca = s2[1], bc = s2[2];
    float4* dst = g_sorted + (size_t)row * NP;
    {
        int bin = binof(ab.x);
        int pos = g_segstart[row][seg][bin] + atomicAdd(&cnt[bin], 1);
        dst[pos] = make_float4(ab.x, ab.y, ca.x,
                               0.5f * (ab.x * ab.x + ab.y * ab.y + ca.x * ca.x));
    }
    {
        int bin = binof(ca.y);
        int pos = g_segstart[row][seg][bin] + atomicAdd(&cnt[bin], 1);
        dst[pos] = make_float4(ca.y, bc.x, bc.y,
                               0.5f * (ca.y * ca.y + bc.x * bc.x + bc.y * bc.y));
    }
}

__global__ __launch_bounds__(BT) void chamfer_kernel(float* __restrict__ out) {
    __shared__ int    sbs[NB + 1];
    __shared__ float4 swin[WCAP];
    __shared__ float4 qbuf[QPB];
    __shared__ float  sdist[QPB];
    __shared__ int    slist[QPB];
    __shared__ float  smin[QPB];
    __shared__ int    scount;
    __shared__ int    wKL[4], wKR[4];
    __shared__ int    wScanLo[4], wScanHi[4];
    __shared__ int    bWinLo, bWinCnt;
    __shared__ int    sIsLast;

    int blk = blockIdx.x;                 // 1024 blocks
    int dir = blk >> 9;
    int b   = (blk >> 5) & 15;
    int qt  = blk & 31;
    int tid = threadIdx.x;
    int lane = tid & 31;
    int wid  = tid >> 5;

    int qRow  = dir ? (16 + b) : b;
    int dbRow = dir ? b : (16 + b);
    const float4* db = g_sorted + (size_t)dbRow * NP;

    for (int k = tid; k <= NB; k += BT) sbs[k] = g_binstart[dbRow][k];
    if (tid == 0) scount = 0;

    float4 q = g_sorted[(size_t)qRow * NP + qt * QPB + tid];
    qbuf[tid] = q;
    __syncthreads();

    // Per-warp window: span of the warp's 32 queries + PAD, count-extended.
    int myBin = binof(q.x);
    int kL = (int)__reduce_min_sync(FULLM, (unsigned)myBin);
    int kR = (int)__reduce_max_sync(FULLM, (unsigned)myBin);
    kL = max(kL - PAD, 0);
    kR = min(kR + PAD, NB - 1);
    while (sbs[kR + 1] - sbs[kL] < WMIN && (kL > 0 || kR < NB - 1)) {
        if (kL > 0) kL--;
        if (kR < NB - 1) kR++;
    }
    if (lane == 0) { wKL[wid] = kL; wKR[wid] = kR; }
    __syncthreads();

    if (tid == 0) {
        int kLb = min(min(wKL[0], wKL[1]), min(wKL[2], wKL[3]));
        int kRb = max(max(wKR[0], wKR[1]), max(wKR[2], wKR[3]));
        int lo  = sbs[kLb];
        bWinLo  = lo;
        bWinCnt = min(sbs[kRb + 1] - lo, WCAP);
    }
    __syncthreads();
    int winLo = bWinLo, winCnt = bWinCnt;

    for (int j = tid; j < winCnt; j += BT) swin[j] = db[winLo + j];

    int sLo = max(sbs[kL] - winLo, 0);
    int sHi = min(sbs[kR + 1] - winLo, winCnt);
    bool clampedL = (sbs[kL] < winLo);
    bool clampedR = (sbs[kR + 1] > winLo + winCnt);
    if (lane == 0) { wScanLo[wid] = winLo + sLo; wScanHi[wid] = winLo + sHi; }
    __syncthreads();

    // min over window of t_j = 0.5|s_j|^2 - q.s_j
    float m0 = 1e30f, m1 = 1e30f, m2 = 1e30f, m3 = 1e30f;
    int j = sLo;
    for (; j + 4 <= sHi; j += 4) {
        float4 p0 = swin[j];
        float4 p1 = swin[j + 1];
        float4 p2 = swin[j + 2];
        float4 p3 = swin[j + 3];
        m0 = fminf(m0, fmaf(-q.x, p0.x, fmaf(-q.y, p0.y, fmaf(-q.z, p0.z, p0.w))));
        m1 = fminf(m1, fmaf(-q.x, p1.x, fmaf(-q.y, p1.y, fmaf(-q.z, p1.z, p1.w))));
        m2 = fminf(m2, fmaf(-q.x, p2.x, fmaf(-q.y, p2.y, fmaf(-q.z, p2.z, p2.w))));
        m3 = fminf(m3, fmaf(-q.x, p3.x, fmaf(-q.y, p3.y, fmaf(-q.z, p3.z, p3.w))));
    }
    for (; j < sHi; ++j) {
        float4 p0 = swin[j];
        m0 = fminf(m0, fmaf(-q.x, p0.x, fmaf(-q.y, p0.y, fmaf(-q.z, p0.z, p0.w))));
    }
    float m = fminf(fminf(m0, m1), fminf(m2, m3));

    // Exact per-lane exclusion bound at warp-window bin edges.
    float thr   = q.w + m;                      // 0.5 * d_best^2 upper bound
    float edgeL = LOV + (float)kL * WBIN;
    float edgeR = LOV + (float)(kR + 1) * WBIN;
    float gl = fmaxf(q.x - edgeL, 0.0f);
    float gr = fmaxf(edgeR - q.x, 0.0f);
    bool dL = !clampedL && ((kL == 0)      || (0.5f * gl * gl >= thr));
    bool dR = !clampedR && ((kR == NB - 1) || (0.5f * gr * gr >= thr));

    sdist[tid] = sqrtf(1e-6f + fmaxf(2.0f * thr, 0.0f));

    bool need = !(dL && dR);
    unsigned mk = __ballot_sync(FULLM, need);
    int nneed = __popc(mk);
    if (nneed) {
        int base = 0;
        if (lane == 0) base = atomicAdd(&scount, nneed);
        base = __shfl_sync(FULLM, base, 0);
        if (need) {
            int rank = __popc(mk & ((1u << lane) - 1));
            slist[base + rank] = tid;
            smin[base + rank] = m;
        }
    }
    __syncthreads();

    // Block-local exact phase 2: one warp per spilled query; skip scanned range.
    int ns = scount;
    for (int i = wid; i < ns; i += BT / 32) {
        int t = slist[i];
        float mm = smin[i];
        float4 q2 = qbuf[t];
        int w2 = t >> 5;
        int skLo = wScanLo[w2], skHi = wScanHi[w2];

        float d1 = sqrtf(fmaxf(2.0f * (q2.w + mm), 0.0f)) * 1.0005f + 1e-5f;
        int lo2 = sbs[binof(q2.x - d1)];
        int hi2 = sbs[binof(q2.x + d1) + 1];

        int hA = min(hi2, skLo);
        for (int jj = lo2 + lane; jj < hA; jj += 32) {
            float4 p = __ldg(&db[jj]);
            mm = fminf(mm, fmaf(-q2.x, p.x, fmaf(-q2.y, p.y, fmaf(-q2.z, p.z, p.w))));
        }
        int lB = max(lo2, skHi);
        for (int jj = lB + lane; jj < hi2; jj += 32) {
            float4 p = __ldg(&db[jj]);
            mm = fminf(mm, fmaf(-q2.x, p.x, fmaf(-q2.y, p.y, fmaf(-q2.z, p.z, p.w))));
        }
        #pragma unroll
        for (int o = 16; o; o >>= 1)
            mm = fminf(mm, __shfl_xor_sync(FULLM, mm, o));
        if (lane == 0)
            sdist[t] = sqrtf(1e-6f + fmaxf(2.0f * (q2.w + mm), 0.0f));
    }
    __syncthreads();

    // Deterministic fixed-tree reduction over the block's 128 distances.
    #pragma unroll
    for (int st = BT / 2; st > 0; st >>= 1) {
        if (tid < st) sdist[tid] += sdist[tid + st];
        __syncthreads();
    }
    if (tid == 0) g_partial[blk] = sdist[0];

    // Fused finalize: last block (atomic ticket) sums all partials.
    __threadfence();
    if (tid == 0) {
        unsigned t = atomicAdd(&g_done, 1u);
        sIsLast = (t == NBLK - 1);
    }
    __syncthreads();
    if (sIsLast) {
        float v = 0.0f;
        #pragma unroll
        for (int i = 0; i < NBLK / BT; i++) v += g_partial[tid + BT * i];
        sdist[tid] = v;
        __syncthreads();
        #pragma unroll
        for (int st = BT / 2; st > 0; st >>= 1) {
            if (tid < st) sdist[tid] += sdist[tid + st];
            __syncthreads();
        }
        if (tid == 0) out[0] = sdist[0] * (1.0f / (float)TOTAL);
    }
}

extern "C" void kernel_launch(void* const* d_in, const int* in_sizes, int n_in,
                              void* d_out, int out_size) {
    const float* x = (const float*)d_in[0];
    const float* y = (const float*)d_in[1];
    float* out = (float*)d_out;

    hist_kernel<<<256, 256>>>(x, y);
    prefix_kernel<<<ROWS, NB>>>();
    scatter_kernel<<<256, 256>>>(x, y);
    chamfer_kernel<<<NBLK, BT>>>(out);
}